// round 1
// baseline (speedup 1.0000x reference)
#include <cuda_runtime.h>
#include <cuda_fp16.h>
#include <cstdint>
#include <cstddef>

// Problem constants
#define NN 16384
#define EE 8192
#define FF 64
static_assert(NN % 128 == 0 && EE % 128 == 0, "tiling");

// ---------------- scratch (device globals; no cudaMalloc allowed) ----------------
__device__ __half g_Hh[(size_t)NN * EE];        // 256 MB fp16 copy of H
__device__ float  g_dvraw[NN];                  // row sums of H
__device__ float  g_dv[NN];                     // rowsum^-0.5
__device__ float  g_depart[256 * EE];           // per-rowchunk partial col sums (8 MB)
__device__ float  g_se[EE];                     // W[e]*2^14/colsum[e]
__device__ __half g_u[(size_t)NN * FF];         // dv * (x@weight), fp16
__device__ float  g_tpart[2 * EE * FF];         // split-k partials of H^T @ u
__device__ __half g_t2[EE * FF];                // se * t, fp16

#define OUT_SCALE 6.103515625e-05f  // 1/16384

// ---------------- PTX helpers ----------------
__device__ __forceinline__ void cp16(void* dst, const void* src) {
    uint32_t d = (uint32_t)__cvta_generic_to_shared(dst);
    asm volatile("cp.async.cg.shared.global [%0], [%1], 16;\n" :: "r"(d), "l"(src));
}
__device__ __forceinline__ void cp_commit() { asm volatile("cp.async.commit_group;\n"); }
template <int n>
__device__ __forceinline__ void cp_wait() { asm volatile("cp.async.wait_group %0;\n" :: "n"(n)); }

__device__ __forceinline__ void ldsm4(uint32_t (&r)[4], const void* p) {
    uint32_t a = (uint32_t)__cvta_generic_to_shared(p);
    asm volatile("ldmatrix.sync.aligned.m8n8.x4.shared.b16 {%0,%1,%2,%3}, [%4];"
                 : "=r"(r[0]), "=r"(r[1]), "=r"(r[2]), "=r"(r[3]) : "r"(a));
}
__device__ __forceinline__ void ldsm4t(uint32_t (&r)[4], const void* p) {
    uint32_t a = (uint32_t)__cvta_generic_to_shared(p);
    asm volatile("ldmatrix.sync.aligned.m8n8.x4.trans.shared.b16 {%0,%1,%2,%3}, [%4];"
                 : "=r"(r[0]), "=r"(r[1]), "=r"(r[2]), "=r"(r[3]) : "r"(a));
}
__device__ __forceinline__ void mma16816(float (&c)[4], const uint32_t (&a)[4],
                                         uint32_t b0, uint32_t b1) {
    asm volatile(
        "mma.sync.aligned.m16n8k16.row.col.f32.f16.f16.f32 "
        "{%0,%1,%2,%3},{%4,%5,%6,%7},{%8,%9},{%0,%1,%2,%3};"
        : "+f"(c[0]), "+f"(c[1]), "+f"(c[2]), "+f"(c[3])
        : "r"(a[0]), "r"(a[1]), "r"(a[2]), "r"(a[3]), "r"(b0), "r"(b1));
}

// ---------------- P0: convert H->fp16, row sums (block-owned), col partial sums ----------------
// grid: 256 blocks * 256 threads; block owns 64 rows x all 8192 cols.
__global__ __launch_bounds__(256) void k_p0(const float* __restrict__ H) {
    const int t = threadIdx.x;
    const int r0 = blockIdx.x * 64;
    float colAcc[32];
#pragma unroll
    for (int j = 0; j < 32; j++) colAcc[j] = 0.f;
    __shared__ float s_red[8];

    for (int r = 0; r < 64; r++) {
        const float4* row4 = (const float4*)(H + (size_t)(r0 + r) * EE);
        uint2* rowh = (uint2*)(g_Hh + (size_t)(r0 + r) * EE);
        float rsum = 0.f;
#pragma unroll
        for (int j = 0; j < 8; j++) {
            float4 v = row4[t + 256 * j];
            __half2 h0 = __floats2half2_rn(v.x, v.y);
            __half2 h1 = __floats2half2_rn(v.z, v.w);
            uint2 uu;
            uu.x = *reinterpret_cast<uint32_t*>(&h0);
            uu.y = *reinterpret_cast<uint32_t*>(&h1);
            rowh[t + 256 * j] = uu;
            colAcc[4 * j + 0] += v.x;
            colAcc[4 * j + 1] += v.y;
            colAcc[4 * j + 2] += v.z;
            colAcc[4 * j + 3] += v.w;
            rsum += (v.x + v.y) + (v.z + v.w);
        }
#pragma unroll
        for (int o = 16; o; o >>= 1) rsum += __shfl_xor_sync(0xffffffffu, rsum, o);
        if ((t & 31) == 0) s_red[t >> 5] = rsum;
        __syncthreads();
        if (t == 0) {
            float s = 0.f;
#pragma unroll
            for (int i = 0; i < 8; i++) s += s_red[i];
            g_dvraw[r0 + r] = s;
        }
        __syncthreads();
    }
    float* dp = g_depart + (size_t)blockIdx.x * EE;
#pragma unroll
    for (int j = 0; j < 8; j++) {
        *(float4*)&dp[4 * t + 1024 * j] =
            make_float4(colAcc[4 * j], colAcc[4 * j + 1], colAcc[4 * j + 2], colAcc[4 * j + 3]);
    }
}

// ---------------- P1: finish de (-> se) and dv ----------------
__global__ __launch_bounds__(256) void k_scales(const float* __restrict__ W) {
    int gid = blockIdx.x * 256 + threadIdx.x;
    if (gid < EE) {
        float s = 0.f;
        for (int p = 0; p < 256; p++) s += g_depart[(size_t)p * EE + gid];
        g_se[gid] = W[gid] * 16384.0f / s;
    }
    if (gid < NN) g_dv[gid] = rsqrtf(g_dvraw[gid]);
}

// ---------------- P2: u = dv * (x @ weight), fp16 ----------------
// 512 blocks * 256 threads; block = 32 rows.
__global__ __launch_bounds__(256) void k_u(const float* __restrict__ x,
                                           const float* __restrict__ w) {
    __shared__ float s_w[64][64];
    __shared__ float s_x[32][64];
    const int t = threadIdx.x;
    const int r0 = blockIdx.x * 32;
    for (int i = t; i < 4096; i += 256) s_w[i >> 6][i & 63] = w[i];
    for (int i = t; i < 2048; i += 256) s_x[i >> 6][i & 63] = x[(size_t)r0 * 64 + i];
    __syncthreads();
    const int row = t >> 3, fb = (t & 7) * 8;
    float acc[8] = {0.f, 0.f, 0.f, 0.f, 0.f, 0.f, 0.f, 0.f};
#pragma unroll
    for (int k = 0; k < 64; k++) {
        float xv = s_x[row][k];
#pragma unroll
        for (int i = 0; i < 8; i++) acc[i] += xv * s_w[k][fb + i];
    }
    float dvn = g_dv[r0 + row];
#pragma unroll
    for (int i = 0; i < 8; i++)
        g_u[(size_t)(r0 + row) * 64 + fb + i] = __float2half_rn(dvn * acc[i]);
}

// ---------------- GEMM1: tpart[split] = (H^T @ u) over half the n-range ----------------
// grid (64, 2); BM=128 (e), BK=32 (n), Ndim=64 (f). A needs transpose -> ldmatrix.trans.
__global__ __launch_bounds__(256) void k_gemm1() {
    __shared__ __half sA[2][32][136];  // [k=n][m=e], stride 272B == 16 mod 128 -> conflict free
    __shared__ __half sB[2][32][72];   // [k=n][f],  stride 144B == 16 mod 128
    const int t = threadIdx.x;
    const int lane = t & 31;
    const int wid = t >> 5;
    const int mb = (wid >> 1) * 32;
    const int nb = (wid & 1) * 32;
    const int e0 = blockIdx.x * 128;
    const size_t kbase = (size_t)blockIdx.y * (NN / 2);
    float c[2][4][4];
#pragma unroll
    for (int i = 0; i < 2; i++)
#pragma unroll
        for (int j = 0; j < 4; j++)
#pragma unroll
            for (int k = 0; k < 4; k++) c[i][j][k] = 0.f;

    const int br = t >> 3, bc = (t & 7) * 8;

    // prologue
    {
        size_t k0 = kbase;
#pragma unroll
        for (int i = 0; i < 2; i++) {
            int q = t + 256 * i, row = q >> 4, co = (q & 15) * 8;
            cp16(&sA[0][row][co], g_Hh + (k0 + row) * (size_t)EE + e0 + co);
        }
        cp16(&sB[0][br][bc], g_u + (k0 + br) * 64 + bc);
        cp_commit();
    }

    const int ITERS = (NN / 2) / 32;  // 256
    for (int it = 0; it < ITERS; ++it) {
        int cur = it & 1;
        if (it + 1 < ITERS) {
            size_t k0 = kbase + (size_t)(it + 1) * 32;
            int nxt = cur ^ 1;
#pragma unroll
            for (int i = 0; i < 2; i++) {
                int q = t + 256 * i, row = q >> 4, co = (q & 15) * 8;
                cp16(&sA[nxt][row][co], g_Hh + (k0 + row) * (size_t)EE + e0 + co);
            }
            cp16(&sB[nxt][br][bc], g_u + (k0 + br) * 64 + bc);
            cp_commit();
            cp_wait<1>();
        } else {
            cp_wait<0>();
        }
        __syncthreads();
#pragma unroll
        for (int ks = 0; ks < 2; ks++) {
            const int kb = ks * 16;
            uint32_t a[2][4], b[2][4];
            {
                int krow = kb + (lane & 7) + ((lane & 16) ? 8 : 0);
                int mc0 = mb + ((lane & 8) ? 8 : 0);
                ldsm4t(a[0], &sA[cur][krow][mc0]);
                ldsm4t(a[1], &sA[cur][krow][mc0 + 16]);
            }
            {
                int krow = kb + (lane & 7) + (lane & 8);
                int nc0 = nb + ((lane & 16) ? 8 : 0);
                ldsm4t(b[0], &sB[cur][krow][nc0]);
                ldsm4t(b[1], &sB[cur][krow][nc0 + 16]);
            }
#pragma unroll
            for (int mi = 0; mi < 2; mi++)
#pragma unroll
                for (int nj = 0; nj < 2; nj++) {
                    mma16816(c[mi][2 * nj], a[mi], b[nj][0], b[nj][1]);
                    mma16816(c[mi][2 * nj + 1], a[mi], b[nj][2], b[nj][3]);
                }
        }
        __syncthreads();
    }

    const int g = lane >> 2, tig = lane & 3;
    float* op = g_tpart + (size_t)blockIdx.y * (EE * 64);
#pragma unroll
    for (int mi = 0; mi < 2; mi++) {
        int e = e0 + mb + mi * 16 + g;
#pragma unroll
        for (int nt = 0; nt < 4; nt++) {
            int f = nb + nt * 8 + 2 * tig;
            *(float2*)&op[(size_t)e * 64 + f] = make_float2(c[mi][nt][0], c[mi][nt][1]);
            *(float2*)&op[(size_t)(e + 8) * 64 + f] = make_float2(c[mi][nt][2], c[mi][nt][3]);
        }
    }
}

// ---------------- P3: t2 = fp16( se[e] * (part0 + part1) ) ----------------
__global__ __launch_bounds__(256) void k_combine() {
    int i = blockIdx.x * 256 + threadIdx.x;  // 0 .. EE*64-1
    int e = i >> 6;
    g_t2[i] = __float2half_rn(g_se[e] * (g_tpart[i] + g_tpart[EE * 64 + i]));
}

// ---------------- GEMM2: out = dv * (H @ t2) / 2^14 + bias ----------------
// grid 128; BM=128 (n rows), BK=32 (e). A is k-contiguous -> plain ldmatrix.
__global__ __launch_bounds__(256) void k_gemm2(const float* __restrict__ bias,
                                               float* __restrict__ out) {
    __shared__ __half sA[2][128][40];  // [m=n][k=e], stride 80B == 16 mod 32 -> conflict free
    __shared__ __half sB[2][32][72];   // [k=e][f]
    const int t = threadIdx.x;
    const int lane = t & 31;
    const int wid = t >> 5;
    const int mb = (wid >> 1) * 32;
    const int nb = (wid & 1) * 32;
    const int m0 = blockIdx.x * 128;
    float c[2][4][4];
#pragma unroll
    for (int i = 0; i < 2; i++)
#pragma unroll
        for (int j = 0; j < 4; j++)
#pragma unroll
            for (int k = 0; k < 4; k++) c[i][j][k] = 0.f;

    const int br = t >> 3, bc = (t & 7) * 8;

    {
        size_t k0 = 0;
#pragma unroll
        for (int i = 0; i < 2; i++) {
            int q = t + 256 * i, row = q >> 2, co = (q & 3) * 8;
            cp16(&sA[0][row][co], g_Hh + (size_t)(m0 + row) * EE + k0 + co);
        }
        cp16(&sB[0][br][bc], g_t2 + (k0 + br) * 64 + bc);
        cp_commit();
    }

    const int ITERS = EE / 32;  // 256
    for (int it = 0; it < ITERS; ++it) {
        int cur = it & 1;
        if (it + 1 < ITERS) {
            size_t k0 = (size_t)(it + 1) * 32;
            int nxt = cur ^ 1;
#pragma unroll
            for (int i = 0; i < 2; i++) {
                int q = t + 256 * i, row = q >> 2, co = (q & 3) * 8;
                cp16(&sA[nxt][row][co], g_Hh + (size_t)(m0 + row) * EE + k0 + co);
            }
            cp16(&sB[nxt][br][bc], g_t2 + (k0 + br) * 64 + bc);
            cp_commit();
            cp_wait<1>();
        } else {
            cp_wait<0>();
        }
        __syncthreads();
#pragma unroll
        for (int ks = 0; ks < 2; ks++) {
            const int kb = ks * 16;
            uint32_t a[2][4], b[2][4];
            {
                int arow = mb + (lane & 15);
                int kc = kb + ((lane & 16) ? 8 : 0);
                ldsm4(a[0], &sA[cur][arow][kc]);
                ldsm4(a[1], &sA[cur][arow + 16][kc]);
            }
            {
                int krow = kb + (lane & 7) + (lane & 8);
                int nc0 = nb + ((lane & 16) ? 8 : 0);
                ldsm4t(b[0], &sB[cur][krow][nc0]);
                ldsm4t(b[1], &sB[cur][krow][nc0 + 16]);
            }
#pragma unroll
            for (int mi = 0; mi < 2; mi++)
#pragma unroll
                for (int nj = 0; nj < 2; nj++) {
                    mma16816(c[mi][2 * nj], a[mi], b[nj][0], b[nj][1]);
                    mma16816(c[mi][2 * nj + 1], a[mi], b[nj][2], b[nj][3]);
                }
        }
        __syncthreads();
    }

    const int g = lane >> 2, tig = lane & 3;
#pragma unroll
    for (int mi = 0; mi < 2; mi++) {
        int n = m0 + mb + mi * 16 + g;
        float dv0 = g_dv[n] * OUT_SCALE;
        float dv8 = g_dv[n + 8] * OUT_SCALE;
#pragma unroll
        for (int nt = 0; nt < 4; nt++) {
            int f = nb + nt * 8 + 2 * tig;
            float b0 = bias[f], b1 = bias[f + 1];
            *(float2*)&out[(size_t)n * 64 + f] =
                make_float2(dv0 * c[mi][nt][0] + b0, dv0 * c[mi][nt][1] + b1);
            *(float2*)&out[(size_t)(n + 8) * 64 + f] =
                make_float2(dv8 * c[mi][nt][2] + b0, dv8 * c[mi][nt][3] + b1);
        }
    }
}

// ---------------- launch ----------------
extern "C" void kernel_launch(void* const* d_in, const int* in_sizes, int n_in,
                              void* d_out, int out_size) {
    (void)in_sizes; (void)n_in; (void)out_size;
    const float* x = (const float*)d_in[0];       // [N,64]
    const float* H = (const float*)d_in[1];       // [N,E]
    const float* W = (const float*)d_in[2];       // [E]
    const float* w = (const float*)d_in[3];       // [64,64]
    const float* b = (const float*)d_in[4];       // [64]
    float* out = (float*)d_out;                   // [N,64]

    k_p0<<<256, 256>>>(H);
    k_scales<<<64, 256>>>(W);
    k_u<<<512, 256>>>(x, w);
    k_gemm1<<<dim3(64, 2), 256>>>();
    k_combine<<<2048, 256>>>();
    k_gemm2<<<128, 256>>>(b, out);
}

// round 2
// speedup vs baseline: 1.5060x; 1.5060x over previous
#include <cuda_runtime.h>
#include <cuda_fp16.h>
#include <cstdint>
#include <cstddef>

// Problem constants
#define NN 16384
#define EE 8192
#define FF 64
#define SPLIT 8
static_assert(NN % 128 == 0 && EE % 128 == 0, "tiling");

// ---------------- scratch (device globals; no cudaMalloc allowed) ----------------
__device__ __half g_Hh[(size_t)NN * EE];        // 256 MB fp16 copy of H
__device__ float  g_dv[NN];                     // rowsum^-0.5
__device__ float  g_departB[SPLIT * EE];        // per-split col sums (from gemm1)
__device__ __half g_u[(size_t)NN * FF];         // dv * (x@weight), fp16
__device__ float  g_tpart[SPLIT * EE * FF];     // split-k partials of H^T @ u (16 MB)
__device__ __half g_t2[EE * FF];                // se * t, fp16

#define OUT_SCALE 6.103515625e-05f  // 1/16384

// ---------------- PTX helpers ----------------
__device__ __forceinline__ void cp16(void* dst, const void* src) {
    uint32_t d = (uint32_t)__cvta_generic_to_shared(dst);
    asm volatile("cp.async.cg.shared.global [%0], [%1], 16;\n" :: "r"(d), "l"(src));
}
__device__ __forceinline__ void cp_commit() { asm volatile("cp.async.commit_group;\n"); }
template <int n>
__device__ __forceinline__ void cp_wait() { asm volatile("cp.async.wait_group %0;\n" :: "n"(n)); }

__device__ __forceinline__ void ldsm4(uint32_t (&r)[4], const void* p) {
    uint32_t a = (uint32_t)__cvta_generic_to_shared(p);
    asm volatile("ldmatrix.sync.aligned.m8n8.x4.shared.b16 {%0,%1,%2,%3}, [%4];"
                 : "=r"(r[0]), "=r"(r[1]), "=r"(r[2]), "=r"(r[3]) : "r"(a));
}
__device__ __forceinline__ void ldsm4t(uint32_t (&r)[4], const void* p) {
    uint32_t a = (uint32_t)__cvta_generic_to_shared(p);
    asm volatile("ldmatrix.sync.aligned.m8n8.x4.trans.shared.b16 {%0,%1,%2,%3}, [%4];"
                 : "=r"(r[0]), "=r"(r[1]), "=r"(r[2]), "=r"(r[3]) : "r"(a));
}
__device__ __forceinline__ void mma16816(float (&c)[4], const uint32_t (&a)[4],
                                         uint32_t b0, uint32_t b1) {
    asm volatile(
        "mma.sync.aligned.m16n8k16.row.col.f32.f16.f16.f32 "
        "{%0,%1,%2,%3},{%4,%5,%6,%7},{%8,%9},{%0,%1,%2,%3};"
        : "+f"(c[0]), "+f"(c[1]), "+f"(c[2]), "+f"(c[3])
        : "r"(a[0]), "r"(a[1]), "r"(a[2]), "r"(a[3]), "r"(b0), "r"(b1));
}

// ---------------- P0: convert H->fp16 + row sums. Warp-owns-row, no __syncthreads ----------------
// grid 512 x 256 threads; block = 32 rows; warp = 4 rows; lane strides cols.
__global__ __launch_bounds__(256) void k_p0(const float* __restrict__ H) {
    const int lane = threadIdx.x & 31;
    const int w = threadIdx.x >> 5;
    const int row0 = blockIdx.x * 32 + w * 4;
#pragma unroll
    for (int rr = 0; rr < 4; rr++) {
        const int row = row0 + rr;
        const float4* __restrict__ src = (const float4*)(H + (size_t)row * EE);
        uint2* __restrict__ dst = (uint2*)(g_Hh + (size_t)row * EE);
        float s = 0.f;
#pragma unroll 8
        for (int j = 0; j < 64; j++) {
            float4 v = src[lane + 32 * j];
            __half2 h0 = __floats2half2_rn(v.x, v.y);
            __half2 h1 = __floats2half2_rn(v.z, v.w);
            uint2 uu;
            uu.x = *reinterpret_cast<uint32_t*>(&h0);
            uu.y = *reinterpret_cast<uint32_t*>(&h1);
            dst[lane + 32 * j] = uu;
            s += (v.x + v.y) + (v.z + v.w);
        }
#pragma unroll
        for (int o = 16; o; o >>= 1) s += __shfl_xor_sync(0xffffffffu, s, o);
        if (lane == 0) g_dv[row] = rsqrtf(s);
    }
}

// ---------------- P2: u = dv * (x @ weight), fp16 ----------------
__global__ __launch_bounds__(256) void k_u(const float* __restrict__ x,
                                           const float* __restrict__ w) {
    __shared__ float s_w[64][64];
    __shared__ float s_x[32][64];
    const int t = threadIdx.x;
    const int r0 = blockIdx.x * 32;
    for (int i = t; i < 4096; i += 256) s_w[i >> 6][i & 63] = w[i];
    for (int i = t; i < 2048; i += 256) s_x[i >> 6][i & 63] = x[(size_t)r0 * 64 + i];
    __syncthreads();
    const int row = t >> 3, fb = (t & 7) * 8;
    float acc[8] = {0.f, 0.f, 0.f, 0.f, 0.f, 0.f, 0.f, 0.f};
#pragma unroll
    for (int k = 0; k < 64; k++) {
        float xv = s_x[row][k];
#pragma unroll
        for (int i = 0; i < 8; i++) acc[i] += xv * s_w[k][fb + i];
    }
    float dvn = g_dv[r0 + row];
#pragma unroll
    for (int i = 0; i < 8; i++)
        g_u[(size_t)(r0 + row) * 64 + fb + i] = __float2half_rn(dvn * acc[i]);
}

// ---------------- GEMM1: tpart[split] = H^T @ u over 1/SPLIT of n, plus col sums ----------------
// grid (EE/128, SPLIT) = (64, 8); BM=128 (e), BN=64 (f), BK=32 (n), 3-stage pipeline.
#define G1_STAGES 3
__global__ __launch_bounds__(256) void k_gemm1() {
    __shared__ __half sA[G1_STAGES][32][136];  // [k=n][m=e], stride 272B
    __shared__ __half sB[G1_STAGES][32][72];   // [k=n][f]
    __shared__ float2 s_red[256];
    const int t = threadIdx.x;
    const int lane = t & 31;
    const int wid = t >> 5;
    const int mb = (wid >> 1) * 32;
    const int nb = (wid & 1) * 32;
    const int e0 = blockIdx.x * 128;
    const size_t kbase = (size_t)blockIdx.y * (NN / SPLIT);
    float c[2][4][4];
#pragma unroll
    for (int i = 0; i < 2; i++)
#pragma unroll
        for (int j = 0; j < 4; j++)
#pragma unroll
            for (int k = 0; k < 4; k++) c[i][j][k] = 0.f;

    const int br = t >> 3, bc = (t & 7) * 8;
    // col-sum side accumulation layout: thread owns col pair (t&63), k-rows (t>>6)*8..+7
    const int cp2 = (t & 63) * 2;
    const int kr0 = (t >> 6) * 8;
    float csx = 0.f, csy = 0.f;

    const int ITERS = (NN / SPLIT) / 32;  // 64

    // prologue: stages 0..G1_STAGES-2
#pragma unroll
    for (int s = 0; s < G1_STAGES - 1; s++) {
        size_t k0 = kbase + (size_t)s * 32;
#pragma unroll
        for (int i = 0; i < 2; i++) {
            int q = t + 256 * i, row = q >> 4, co = (q & 15) * 8;
            cp16(&sA[s][row][co], g_Hh + (k0 + row) * (size_t)EE + e0 + co);
        }
        cp16(&sB[s][br][bc], g_u + (k0 + br) * 64 + bc);
        cp_commit();
    }

    for (int it = 0; it < ITERS; ++it) {
        cp_wait<G1_STAGES - 2>();
        __syncthreads();
        const int cur = it % G1_STAGES;
        // issue next stage
        if (it + G1_STAGES - 1 < ITERS) {
            const int nxt = (it + G1_STAGES - 1) % G1_STAGES;
            size_t k0 = kbase + (size_t)(it + G1_STAGES - 1) * 32;
#pragma unroll
            for (int i = 0; i < 2; i++) {
                int q = t + 256 * i, row = q >> 4, co = (q & 15) * 8;
                cp16(&sA[nxt][row][co], g_Hh + (k0 + row) * (size_t)EE + e0 + co);
            }
            cp16(&sB[nxt][br][bc], g_u + (k0 + br) * 64 + bc);
        }
        cp_commit();
        // compute
#pragma unroll
        for (int ks = 0; ks < 2; ks++) {
            const int kb = ks * 16;
            uint32_t a[2][4], b[2][4];
            {
                int krow = kb + (lane & 7) + ((lane & 16) ? 8 : 0);
                int mc0 = mb + ((lane & 8) ? 8 : 0);
                ldsm4t(a[0], &sA[cur][krow][mc0]);
                ldsm4t(a[1], &sA[cur][krow][mc0 + 16]);
            }
            {
                int krow = kb + (lane & 7) + (lane & 8);
                int nc0 = nb + ((lane & 16) ? 8 : 0);
                ldsm4t(b[0], &sB[cur][krow][nc0]);
                ldsm4t(b[1], &sB[cur][krow][nc0 + 16]);
            }
#pragma unroll
            for (int mi = 0; mi < 2; mi++)
#pragma unroll
                for (int nj = 0; nj < 2; nj++) {
                    mma16816(c[mi][2 * nj], a[mi], b[nj][0], b[nj][1]);
                    mma16816(c[mi][2 * nj + 1], a[mi], b[nj][2], b[nj][3]);
                }
        }
        // col-sum side accumulation (fma pipe is idle)
#pragma unroll
        for (int kk = 0; kk < 8; kk++) {
            __half2 v = *(const __half2*)&sA[cur][kr0 + kk][cp2];
            float2 f = __half22float2(v);
            csx += f.x;
            csy += f.y;
        }
    }

    // reduce col sums across the 4 k-row groups
    s_red[t] = make_float2(csx, csy);
    __syncthreads();
    if (t < 64) {
        float2 a0 = s_red[t], a1 = s_red[t + 64], a2 = s_red[t + 128], a3 = s_red[t + 192];
        float2 r = make_float2(a0.x + a1.x + a2.x + a3.x, a0.y + a1.y + a2.y + a3.y);
        *(float2*)&g_departB[(size_t)blockIdx.y * EE + e0 + 2 * t] = r;
    }

    const int g = lane >> 2, tig = lane & 3;
    float* op = g_tpart + (size_t)blockIdx.y * (EE * 64);
#pragma unroll
    for (int mi = 0; mi < 2; mi++) {
        int e = e0 + mb + mi * 16 + g;
#pragma unroll
        for (int nt = 0; nt < 4; nt++) {
            int f = nb + nt * 8 + 2 * tig;
            *(float2*)&op[(size_t)e * 64 + f] = make_float2(c[mi][nt][0], c[mi][nt][1]);
            *(float2*)&op[(size_t)(e + 8) * 64 + f] = make_float2(c[mi][nt][2], c[mi][nt][3]);
        }
    }
}

// ---------------- P3: t2 = fp16( se[e] * sum_s tpart[s] ),  se = W*2^14/colsum ----------------
__global__ __launch_bounds__(256) void k_combine(const float* __restrict__ W) {
    int idx = blockIdx.x * 256 + threadIdx.x;  // float4 index, 0 .. EE*16-1
    int e = idx >> 4;
    float cs = 0.f;
#pragma unroll
    for (int s = 0; s < SPLIT; s++) cs += g_departB[(size_t)s * EE + e];
    float se = W[e] * 16384.0f / cs;
    const float4* tp = (const float4*)g_tpart;
    float4 acc = tp[idx];
#pragma unroll
    for (int s = 1; s < SPLIT; s++) {
        float4 v = tp[(size_t)s * (EE * 16) + idx];
        acc.x += v.x; acc.y += v.y; acc.z += v.z; acc.w += v.w;
    }
    __half2 h0 = __floats2half2_rn(se * acc.x, se * acc.y);
    __half2 h1 = __floats2half2_rn(se * acc.z, se * acc.w);
    uint2 uu;
    uu.x = *reinterpret_cast<uint32_t*>(&h0);
    uu.y = *reinterpret_cast<uint32_t*>(&h1);
    ((uint2*)g_t2)[idx] = uu;
}

// ---------------- GEMM2: out = dv * (H @ t2) / 2^14 + bias ----------------
// grid 256; BM=64 (n rows), BN=64 (f), BK=32 (e), 4-stage pipeline.
#define G2_STAGES 4
__global__ __launch_bounds__(256) void k_gemm2(const float* __restrict__ bias,
                                               float* __restrict__ out) {
    __shared__ __half sA[G2_STAGES][64][40];  // [m=n][k=e], stride 80B
    __shared__ __half sB[G2_STAGES][32][72];  // [k=e][f]
    const int t = threadIdx.x;
    const int lane = t & 31;
    const int wid = t >> 5;
    const int mb = (wid >> 2) * 32;   // 2 m-warps
    const int nb = (wid & 3) * 16;    // 4 n-warps
    const int m0 = blockIdx.x * 64;
    float c[2][2][4];
#pragma unroll
    for (int i = 0; i < 2; i++)
#pragma unroll
        for (int j = 0; j < 2; j++)
#pragma unroll
            for (int k = 0; k < 4; k++) c[i][j][k] = 0.f;

    const int ar = t >> 2, ac = (t & 3) * 8;
    const int br = t >> 3, bc = (t & 7) * 8;
    const int ITERS = EE / 32;  // 256

#pragma unroll
    for (int s = 0; s < G2_STAGES - 1; s++) {
        size_t k0 = (size_t)s * 32;
        cp16(&sA[s][ar][ac], g_Hh + (size_t)(m0 + ar) * EE + k0 + ac);
        cp16(&sB[s][br][bc], g_t2 + (k0 + br) * 64 + bc);
        cp_commit();
    }

    for (int it = 0; it < ITERS; ++it) {
        cp_wait<G2_STAGES - 2>();
        __syncthreads();
        const int cur = it % G2_STAGES;
        if (it + G2_STAGES - 1 < ITERS) {
            const int nxt = (it + G2_STAGES - 1) % G2_STAGES;
            size_t k0 = (size_t)(it + G2_STAGES - 1) * 32;
            cp16(&sA[nxt][ar][ac], g_Hh + (size_t)(m0 + ar) * EE + k0 + ac);
            cp16(&sB[nxt][br][bc], g_t2 + (k0 + br) * 64 + bc);
        }
        cp_commit();
#pragma unroll
        for (int ks = 0; ks < 2; ks++) {
            const int kb = ks * 16;
            uint32_t a[2][4], b[4];
            {
                int arow = mb + (lane & 15);
                int kc = kb + ((lane & 16) ? 8 : 0);
                ldsm4(a[0], &sA[cur][arow][kc]);
                ldsm4(a[1], &sA[cur][arow + 16][kc]);
            }
            {
                int krow = kb + (lane & 7) + (lane & 8);
                int nc0 = nb + ((lane & 16) ? 8 : 0);
                ldsm4t(b, &sB[cur][krow][nc0]);
            }
#pragma unroll
            for (int mi = 0; mi < 2; mi++) {
                mma16816(c[mi][0], a[mi], b[0], b[1]);
                mma16816(c[mi][1], a[mi], b[2], b[3]);
            }
        }
    }

    const int g = lane >> 2, tig = lane & 3;
#pragma unroll
    for (int mi = 0; mi < 2; mi++) {
        int n = m0 + mb + mi * 16 + g;
        float dv0 = g_dv[n] * OUT_SCALE;
        float dv8 = g_dv[n + 8] * OUT_SCALE;
#pragma unroll
        for (int nt = 0; nt < 2; nt++) {
            int f = nb + nt * 8 + 2 * tig;
            float b0 = bias[f], b1 = bias[f + 1];
            *(float2*)&out[(size_t)n * 64 + f] =
                make_float2(dv0 * c[mi][nt][0] + b0, dv0 * c[mi][nt][1] + b1);
            *(float2*)&out[(size_t)(n + 8) * 64 + f] =
                make_float2(dv8 * c[mi][nt][2] + b0, dv8 * c[mi][nt][3] + b1);
        }
    }
}

// ---------------- launch ----------------
extern "C" void kernel_launch(void* const* d_in, const int* in_sizes, int n_in,
                              void* d_out, int out_size) {
    (void)in_sizes; (void)n_in; (void)out_size;
    const float* x = (const float*)d_in[0];       // [N,64]
    const float* H = (const float*)d_in[1];       // [N,E]
    const float* W = (const float*)d_in[2];       // [E]
    const float* w = (const float*)d_in[3];       // [64,64]
    const float* b = (const float*)d_in[4];       // [64]
    float* out = (float*)d_out;                   // [N,64]

    k_p0<<<512, 256>>>(H);
    k_u<<<512, 256>>>(x, w);
    k_gemm1<<<dim3(64, SPLIT), 256>>>();
    k_combine<<<512, 256>>>(W);
    k_gemm2<<<256, 256>>>(b, out);
}